// round 10
// baseline (speedup 1.0000x reference)
#include <cuda_runtime.h>
#include <math.h>

#define IMG   512
#define NVIEW 180
#define NPIX  (IMG * IMG)

typedef unsigned long long ull;

// Interleaved copy of both batch images: g_xi[y*512+x] = (batch0, batch1).
__device__ float2 g_xi[NPIX];

struct Params {
    float2 cs[NVIEW];            // (cos, sin) per view, fp32 from double (matches numpy)
    unsigned char lw[NVIEW];     // tile shape per view
};

// ---- packed f32x2 helpers (sm_100+) ----
__device__ __forceinline__ ull pk(float lo, float hi) {
    ull r; asm("mov.b64 %0,{%1,%2};" : "=l"(r) : "f"(lo), "f"(hi)); return r;
}
__device__ __forceinline__ void upk(ull p, float& lo, float& hi) {
    asm("mov.b64 {%0,%1},%2;" : "=f"(lo), "=f"(hi) : "l"(p));
}
__device__ __forceinline__ ull mul2(ull a, ull b) {
    ull r; asm("mul.rn.f32x2 %0,%1,%2;" : "=l"(r) : "l"(a), "l"(b)); return r;
}
__device__ __forceinline__ ull add2(ull a, ull b) {
    ull r; asm("add.rn.f32x2 %0,%1,%2;" : "=l"(r) : "l"(a), "l"(b)); return r;
}
__device__ __forceinline__ ull fma2(ull a, ull b, ull c) {
    ull r; asm("fma.rn.f32x2 %0,%1,%2,%3;" : "=l"(r) : "l"(a), "l"(b), "l"(c)); return r;
}

// Interleave prep (4 pixels/thread, 128-bit ld/st) + zero the output buffer
// (radon half-blocks accumulate partial sums with atomicAdd).
__global__ __launch_bounds__(256) void prep_kernel(const float* __restrict__ x,
                                                   float* __restrict__ out) {
    int i = blockIdx.x * blockDim.x + threadIdx.x;           // 65536 threads
    const float4* a4 = (const float4*)x;                      // batch 0
    const float4* b4 = (const float4*)(x + NPIX);             // batch 1
    float4 a = a4[i];
    float4 b = b4[i];
    float4* o = (float4*)&g_xi[i * 4];
    o[0] = make_float4(a.x, b.x, a.y, b.y);
    o[1] = make_float4(a.z, b.z, a.w, b.w);
    if (i < (2 * NVIEW * IMG) / 4) {                          // 184320 floats
        ((float4*)out)[i] = make_float4(0.f, 0.f, 0.f, 0.f);
    }
}

// Warp tile: W lanes along w, H = 32/W lanes along h; warp makes 16 outputs
// (NC chunks). Outer iteration 'to' covers rows [8*to, 8*to+8); this body
// handles to in [lo, hi_), further clipped by the conservative valid window
// (skip only if ALL lanes certainly invalid: s>=0 on [0,pi) and the -1 clamp
// maps to valid index 0, so invalid only when gx>1 or gy>1; both monotone in
// h). Two half-blocks combine via atomicAdd into a zeroed cell (2 commutative
// adds -> deterministic).
template<int LOGW>
__device__ __forceinline__ void radon_body(float* __restrict__ out, int v, float2 cs,
                                           int lo, int hi_) {
    constexpr int W  = 1 << LOGW;
    constexpr int H  = 32 >> LOGW;
    constexpr int NC = 16 / W;     // w-chunks per warp
    constexpr int G  = W / 4;      // h-steps per outer iter (G*NC == 4)

    const int lane = threadIdx.x & 31;
    const int warp = threadIdx.x >> 5;
    const int wi   = lane & (W - 1);
    const int hi   = lane >> LOGW;
    const int wbase = ((blockIdx.x & 7) << 6) + (warp << 4);

    const float c = cs.x, s = cs.y;
    const ull csP  = pk(s, c);          // (s, c)
    const ull sgnP = pk(-1.0f, 1.0f);   // gx = P - s*gy0 ; gy = S + c*gy0

    ull PS[NC], acc[NC];
    #pragma unroll
    for (int j = 0; j < NC; j++) {
        int w = wbase + j * W + wi;
        float gx0 = __fmaf_rn((float)w, 1.0f / 256.0f, -511.0f / 512.0f);  // exact
        PS[j] = pk(__fmul_rn(c, gx0), __fmul_rn(s, gx0));   // (P, S)
        acc[j] = 0ull;
    }

    // ---- conservative per-warp valid window over outer iterations ----
    int to_s = lo, to_e = hi_;
    {
        float gx0a = __fmaf_rn((float)wbase,        1.0f / 256.0f, -511.0f / 512.0f);
        float gx0b = __fmaf_rn((float)(wbase + 15), 1.0f / 256.0f, -511.0f / 512.0f);
        float m1 = fminf(c * gx0a, c * gx0b);   // min over lanes of c*gx0
        float M2 = fminf(s * gx0a, s * gx0b);   // min over lanes of s*gx0
        if (s > 1e-6f && m1 > 1.0f) {           // all-gx-invalid for to < T
            float T = (256.0f * (m1 - 1.0f) / s + 248.5f) * 0.125f;
            int t = (int)floorf(T) - 1;
            if (t > to_s) to_s = t;
        }
        if (c < -1e-6f) {                       // c<0: gy decreasing in h
            float T = (256.0f * (1.0f - M2) / c + 248.5f) * 0.125f;
            int t = (int)floorf(T) - 1;
            if (t > to_s) to_s = t;
        } else if (c > 1e-6f) {                 // c>0: gy increasing in h
            float T = (256.0f * (1.0f - M2) / c + 255.5f) * 0.125f;
            int t = (int)ceilf(T) + 2;
            if (t < to_e) to_e = t;
        }
        if (to_s < lo) to_s = lo;
        if (to_e > hi_) to_e = hi_;
        if (to_e < to_s) to_e = to_s;
    }

    // gy0 starts at h = hi + 8*to_s; all values and increments exact in fp32
    float gy0 = __fmaf_rn((float)(hi + 8 * to_s), 1.0f / 256.0f, -511.0f / 512.0f);
    ull gy0p = pk(gy0, gy0);
    const ull stepP = pk((float)H / 256.0f, (float)H / 256.0f);

    const float MAGIC = 12582912.0f;      // 1.5*2^23: magic round-half-even
    const float BOUND = 12583424.0f;      // MAGIC + 512
    const ull ONE2 = pk(1.0f, 1.0f);
    const ull C256 = pk(256.0f, 256.0f);
    const ull MH2  = pk(-0.5f, -0.5f);
    const ull MAG2 = pk(MAGIC, MAGIC);

    #pragma unroll 1
    for (int to = to_s; to < to_e; to++) {
        #pragma unroll
        for (int g = 0; g < G; g++) {
            ull qp = mul2(gy0p, csP);         // (s*gy0, c*gy0), each rounded once
            gy0p = add2(gy0p, stepP);         // exact
            #pragma unroll
            for (int j = 0; j < NC; j++) {
                ull gp = fma2(qp, sgnP, PS[j]);   // (fl(P - s*gy0), fl(S + c*gy0))
                ull up = add2(gp, ONE2);          // fl(clamp(g,-1)+1) == fmax(fl(g+1),0)
                float ux, uy; upk(up, ux, uy);
                ux = fmaxf(ux, 0.0f);
                uy = fmaxf(uy, 0.0f);
                // ((g+1)*512-1)*0.5 == fma(u,256,-0.5) exactly; +MAGIC = rint(ties-even)
                ull rp = add2(fma2(pk(ux, uy), C256, MH2), MAG2);
                float rx, ry; upk(rp, rx, ry);
                bool ok = fmaxf(rx, ry) < BOUND;  // ix,iy >= 0 guaranteed by clamp
                unsigned idx = (unsigned)__float_as_int(ry) * 512u
                             + (unsigned)__float_as_int(rx)
                             - 0x4B400000u * 513u;
                ull val = 0ull;
                if (ok) val = __ldg((const ull*)((const char*)g_xi + (size_t)idx * 8u));
                acc[j] = add2(acc[j], val);
            }
        }
    }

    // reduce over the H h-lanes of each chunk, then accumulate into out
    #pragma unroll
    for (int j = 0; j < NC; j++) {
        float a0, a1; upk(acc[j], a0, a1);
        #pragma unroll
        for (int off = W; off < 32; off <<= 1) {
            a0 += __shfl_xor_sync(0xffffffffu, a0, off);
            a1 += __shfl_xor_sync(0xffffffffu, a1, off);
        }
        if (hi == 0) {
            int w = wbase + j * W + wi;
            atomicAdd(&out[v * IMG + w],               a0 * (1.0f / 512.0f));
            atomicAdd(&out[NVIEW * IMG + v * IMG + w], a1 * (1.0f / 512.0f));
        }
    }
}

// Half-view blocks for dynamic load balancing: grid (16, 180) = 2880 blocks
// vs 11 blocks/SM * 148 SMs = 1628 slots -> ~1.8 waves. Finished SMs refill
// with new blocks, so hard (45-degree) halves backfill behind cheap clipped
// halves instead of bounding a monolithic wave.
__global__ __launch_bounds__(128, 11) void radon_kernel(float* __restrict__ out, Params p) {
    const int v    = blockIdx.y;
    const int half = blockIdx.x >> 3;
    const float2 cs = p.cs[v];
    const int lo = 32 * half, hi_ = lo + 32;
    switch (p.lw[v]) {
        case 2: radon_body<2>(out, v, cs, lo, hi_); break;
        case 3: radon_body<3>(out, v, cs, lo, hi_); break;
        default: radon_body<4>(out, v, cs, lo, hi_); break;
    }
}

extern "C" void kernel_launch(void* const* d_in, const int* in_sizes, int n_in,
                              void* d_out, int out_size) {
    const float* x = (const float*)d_in[0];
    float* out = (float*)d_out;

    prep_kernel<<<NPIX / 4 / 256, 256>>>(x, out);

    // Host-side trig (exactly numpy's fp32 cast) + tile-shape selection.
    static Params p;
    for (int v = 0; v < NVIEW; v++) {
        double th = (double)v * (M_PI / 180.0);
        p.cs[v] = make_float2((float)cos(th), (float)sin(th));
        double ac = fabs(cos(th)), as = fabs(sin(th));
        int best = 2; double bestcost = 1e30;
        for (int lw = 2; lw <= 4; lw++) {
            double W = (double)(1 << lw), H = 32.0 / W;
            double rows = W * as + H * ac + 1.0;
            double segB = (W * ac + H * as) * 8.0 + 8.0;
            double cc = rows * (1.0 + segB / 128.0);
            if (cc < bestcost) { bestcost = cc; best = lw; }
        }
        p.lw[v] = (unsigned char)best;
    }

    dim3 grid(16, NVIEW);
    radon_kernel<<<grid, 128>>>(out, p);
}

// round 11
// speedup vs baseline: 1.0427x; 1.0427x over previous
#include <cuda_runtime.h>
#include <math.h>

#define IMG   512
#define NVIEW 180
#define NPIX  (IMG * IMG)

typedef unsigned long long ull;

// F[y][x] = (b0[y][x], b1[y][x], b0[511-y][x], b1[511-y][x]) : one 16B load
// serves both batches of view v AND of its mirror view 180-v.
__device__ float4 g_xf[NPIX];

struct Params {
    float2 cs[NVIEW];            // (cos, sin) per view, fp32 from double (matches numpy)
    unsigned char lw[NVIEW];     // tile shape per view
    int paired;                  // 1 if mirror-trig verified bitwise on host
};

// ---- packed f32x2 helpers (sm_100+) ----
__device__ __forceinline__ ull pk(float lo, float hi) {
    ull r; asm("mov.b64 %0,{%1,%2};" : "=l"(r) : "f"(lo), "f"(hi)); return r;
}
__device__ __forceinline__ void upk(ull p, float& lo, float& hi) {
    asm("mov.b64 {%0,%1},%2;" : "=f"(lo), "=f"(hi) : "l"(p));
}
__device__ __forceinline__ ull mul2(ull a, ull b) {
    ull r; asm("mul.rn.f32x2 %0,%1,%2;" : "=l"(r) : "l"(a), "l"(b)); return r;
}
__device__ __forceinline__ ull add2(ull a, ull b) {
    ull r; asm("add.rn.f32x2 %0,%1,%2;" : "=l"(r) : "l"(a), "l"(b)); return r;
}
__device__ __forceinline__ ull fma2(ull a, ull b, ull c) {
    ull r; asm("fma.rn.f32x2 %0,%1,%2,%3;" : "=l"(r) : "l"(a), "l"(b), "l"(c)); return r;
}

// Build F and zero the output (radon half-blocks combine via atomicAdd).
__global__ __launch_bounds__(256) void prep_kernel(const float* __restrict__ x,
                                                   float* __restrict__ out) {
    int i = blockIdx.x * blockDim.x + threadIdx.x;    // 65536 threads
    int y  = i >> 7;            // 0..511
    int x4 = i & 127;           // float4-group within row
    const float4* B0 = (const float4*)x;
    const float4* B1 = (const float4*)(x + NPIX);
    float4 a  = B0[y * 128 + x4];
    float4 b  = B1[y * 128 + x4];
    float4 am = B0[(511 - y) * 128 + x4];
    float4 bm = B1[(511 - y) * 128 + x4];
    float4* o = &g_xf[(y << 9) + (x4 << 2)];
    o[0] = make_float4(a.x, b.x, am.x, bm.x);
    o[1] = make_float4(a.y, b.y, am.y, bm.y);
    o[2] = make_float4(a.z, b.z, am.z, bm.z);
    o[3] = make_float4(a.w, b.w, am.w, bm.w);
    if (i < (2 * NVIEW * IMG) / 4) {                  // 184320 floats
        ((float4*)out)[i] = make_float4(0.f, 0.f, 0.f, 0.f);
    }
}

// Paired body: handles output (vA, w) and, if hasB, (vB=180-vA, 511-w) with a
// shared gather. Bitwise-proven (given cs[vB]==(-c,s)):
//   gx(vB,511-w,h) == gx(vA,w,h)      -> shared ix
//   gy(vB,511-w,h) == -gy(vA,w,h)     -> iyB independently computed via the
// exact mirrored chain; usually iyB == 511-iyA so F[iyA].zw supplies B, with a
// rare exact repair load otherwise (ties). Validity: invalid only if gx>1 or
// (own) gy>1 (s>=0; -1 clamp maps to valid index 0). gx>1 is shared -> the
// per-warp clip window (start side; gx decreasing in h) is valid for both.
template<int LOGW>
__device__ __forceinline__ void radon_pair_body(float* __restrict__ out,
                                                int vA, int vB, bool hasB,
                                                float2 cs, int lo, int hi_) {
    constexpr int W  = 1 << LOGW;
    constexpr int H  = 32 >> LOGW;
    constexpr int NC = 16 / W;     // w-chunks per warp
    constexpr int G  = W / 4;      // h-steps per outer iter (G*NC == 4)

    const int lane = threadIdx.x & 31;
    const int warp = threadIdx.x >> 5;
    const int wi   = lane & (W - 1);
    const int hi   = lane >> LOGW;
    const int wbase = ((blockIdx.x & 7) << 6) + (warp << 4);

    const float c = cs.x, s = cs.y;
    const ull csP  = pk(s, c);          // (s, c)
    const ull sgnP = pk(-1.0f, 1.0f);   // gx = P - s*gy0 ; gy = S + c*gy0

    ull PS[NC], accA[NC], accB[NC];
    #pragma unroll
    for (int j = 0; j < NC; j++) {
        int w = wbase + j * W + wi;
        float gx0 = __fmaf_rn((float)w, 1.0f / 256.0f, -511.0f / 512.0f);  // exact
        PS[j] = pk(__fmul_rn(c, gx0), __fmul_rn(s, gx0));   // (P, S)
        accA[j] = 0ull; accB[j] = 0ull;
    }

    // gx-clip (valid for BOTH views): all lanes gx>1 while gy0 < (m1-1)/s.
    int to_s = lo, to_e = hi_;
    if (s > 1e-6f) {
        float gx0a = __fmaf_rn((float)wbase,        1.0f / 256.0f, -511.0f / 512.0f);
        float gx0b = __fmaf_rn((float)(wbase + 15), 1.0f / 256.0f, -511.0f / 512.0f);
        float m1 = fminf(c * gx0a, c * gx0b);   // min over lanes of c*gx0
        float hT = (m1 - 1.0f) / s * 256.0f + 255.5f;   // h below this: all-invalid
        int t = (int)floorf(hT * 0.125f) - 1;           // conservative margin
        if (t > to_s) to_s = t;
        if (to_e < to_s) to_e = to_s;
    }

    // gy0 starts at h = hi + 8*to_s; all values and increments exact in fp32
    float gy0 = __fmaf_rn((float)(hi + 8 * to_s), 1.0f / 256.0f, -511.0f / 512.0f);
    ull gy0p = pk(gy0, gy0);
    const ull stepP = pk((float)H / 256.0f, (float)H / 256.0f);

    const float MAGIC = 12582912.0f;      // 1.5*2^23: magic round-half-even
    const float BOUND = 12583424.0f;      // MAGIC + 512
    const unsigned MAGICI = 0x4B400000u;
    const unsigned ROWSUM = 0x96800000u + 511u;   // 2*MAGICI + 511
    const unsigned OFF    = MAGICI * 513u;        // (mod 2^32)
    const ull ONE2 = pk(1.0f, 1.0f);
    const ull C256 = pk(256.0f, 256.0f);
    const ull MH2  = pk(-0.5f, -0.5f);
    const ull MAG2 = pk(MAGIC, MAGIC);

    #pragma unroll 1
    for (int to = to_s; to < to_e; to++) {
        #pragma unroll
        for (int g = 0; g < G; g++) {
            ull qp = mul2(gy0p, csP);         // (s*gy0, c*gy0), each rounded once
            gy0p = add2(gy0p, stepP);         // exact
            #pragma unroll
            for (int j = 0; j < NC; j++) {
                ull gp = fma2(qp, sgnP, PS[j]);   // (gx, gyA) = ref-exact
                float gxv, gyv; upk(gp, gxv, gyv);
                // A chain (packed): fl(clamp(g,-1)+1) == fmax(fl(g+1),0)
                ull up = add2(gp, ONE2);
                float ux, uyA; upk(up, ux, uyA);
                ux  = fmaxf(ux, 0.0f);
                uyA = fmaxf(uyA, 0.0f);
                ull rp = add2(fma2(pk(ux, uyA), C256, MH2), MAG2);
                float rx, ryA; upk(rp, rx, ryA);
                // B chain (exact, independent): gyB_raw = -gyA (bitwise)
                float uyB = fmaxf(__fsub_rn(1.0f, gyv), 0.0f);   // fl(gyB+1) clamped
                float ryB = __fadd_rn(__fmaf_rn(uyB, 256.0f, -0.5f), MAGIC);
                bool okA = fmaxf(rx, ryA) < BOUND;
                bool okB = fmaxf(rx, ryB) < BOUND;
                unsigned ra  = __float_as_uint(ryA);
                unsigned rb  = __float_as_uint(ryB);
                unsigned rxb = __float_as_uint(rx);
                // load row serves A if valid, else B's mirrored row
                unsigned rowB = okA ? ra : (ROWSUM - rb);
                unsigned idx  = rowB * 512u + rxb - OFF;
                unsigned idxS = (okA | okB) ? idx : 0u;    // safe addr when both invalid
                float4 val = __ldg(&g_xf[idxS]);
                if (okA) accA[j] = add2(accA[j], pk(val.x, val.y));
                bool match = (rowB + rb == ROWSUM);        // iyB == 511 - rowLoaded
                ull bv = pk(val.z, val.w);
                if (__any_sync(0xffffffffu, okB && !match)) {   // rare (ties)
                    unsigned idx2 = (okB && !match) ? (rb * 512u + rxb - OFF) : 0u;
                    float4 v2 = __ldg(&g_xf[idx2]);
                    if (okB && !match) bv = pk(v2.x, v2.y);
                }
                if (okB) accB[j] = add2(accB[j], bv);
            }
        }
    }

    // reduce over the H h-lanes, then atomically accumulate (2 adds/cell ->
    // commutative -> deterministic; out zeroed in prep)
    #pragma unroll
    for (int j = 0; j < NC; j++) {
        float a0, a1; upk(accA[j], a0, a1);
        float b0, b1; upk(accB[j], b0, b1);
        #pragma unroll
        for (int off = W; off < 32; off <<= 1) {
            a0 += __shfl_xor_sync(0xffffffffu, a0, off);
            a1 += __shfl_xor_sync(0xffffffffu, a1, off);
            b0 += __shfl_xor_sync(0xffffffffu, b0, off);
            b1 += __shfl_xor_sync(0xffffffffu, b1, off);
        }
        if (hi == 0) {
            int w = wbase + j * W + wi;
            atomicAdd(&out[vA * IMG + w],               a0 * (1.0f / 512.0f));
            atomicAdd(&out[NVIEW * IMG + vA * IMG + w], a1 * (1.0f / 512.0f));
            if (hasB) {
                int wm = 511 - w;
                atomicAdd(&out[vB * IMG + wm],               b0 * (1.0f / 512.0f));
                atomicAdd(&out[NVIEW * IMG + vB * IMG + wm], b1 * (1.0f / 512.0f));
            }
        }
    }
}

// Paired: grid (16, 91): slots 0..90 = views 0..90 (+ mirror 180-v for 1..89).
// Fallback (paired==0): grid (16, 180), each view alone.
// bx = wblock(0..7) | half<<3; half-h blocks give balance + refill.
__global__ __launch_bounds__(128, 10) void radon_kernel(float* __restrict__ out, Params p) {
    const int vA = blockIdx.y;
    const int vB = NVIEW - vA;
    const bool hasB = p.paired && (vB < NVIEW) && (vB != vA);
    const int half = blockIdx.x >> 3;
    const int lo = 32 * half, hi_ = lo + 32;
    const float2 cs = p.cs[vA];
    switch (p.lw[vA]) {
        case 2: radon_pair_body<2>(out, vA, vB, hasB, cs, lo, hi_); break;
        case 3: radon_pair_body<3>(out, vA, vB, hasB, cs, lo, hi_); break;
        default: radon_pair_body<4>(out, vA, vB, hasB, cs, lo, hi_); break;
    }
}

extern "C" void kernel_launch(void* const* d_in, const int* in_sizes, int n_in,
                              void* d_out, int out_size) {
    const float* x = (const float*)d_in[0];
    float* out = (float*)d_out;

    prep_kernel<<<256, 256>>>(x, out);

    static Params p;
    for (int v = 0; v < NVIEW; v++) {
        double th = (double)v * (M_PI / 180.0);
        p.cs[v] = make_float2((float)cos(th), (float)sin(th));
        double ac = fabs(cos(th)), as = fabs(sin(th));
        int best = 2; double bestcost = 1e30;
        for (int lw = 2; lw <= 4; lw++) {
            double W = (double)(1 << lw), H = 32.0 / W;
            double rows = W * as + H * ac + 1.0;
            double segB = (W * ac + H * as) * 16.0 + 16.0;   // 16B pixels now
            double cc = rows * (1.0 + segB / 128.0);
            if (cc < bestcost) { bestcost = cc; best = lw; }
        }
        p.lw[v] = (unsigned char)best;
    }
    // Verify the mirror-trig identity bitwise (expected to always hold).
    p.paired = 1;
    for (int v = 1; v <= 89; v++) {
        float2 a = p.cs[v], b = p.cs[NVIEW - v];
        if (b.x != -a.x || b.y != a.y) { p.paired = 0; break; }
    }

    dim3 grid(16, p.paired ? 91 : NVIEW);
    radon_kernel<<<grid, 128>>>(out, p);
}

// round 12
// speedup vs baseline: 1.0518x; 1.0087x over previous
#include <cuda_runtime.h>
#include <math.h>
#include <algorithm>

#define IMG   512
#define NVIEW 180
#define NPIX  (IMG * IMG)
#define MAXITEMS 2880

typedef unsigned long long ull;

// F[y][x] = (b0[y][x], b1[y][x], b0[511-y][x], b1[511-y][x]) : one 16B load
// serves both batches of view v AND of its mirror view 180-v.
__device__ float4 g_xf[NPIX];

struct Params {
    float2 cs[NVIEW];              // (cos, sin) per view (fp32 of numpy doubles)
    unsigned char lw[NVIEW];       // tile shape per view
    unsigned short items[MAXITEMS];// cost-sorted work items
};

// ---- packed f32x2 helpers (sm_100+) ----
__device__ __forceinline__ ull pk(float lo, float hi) {
    ull r; asm("mov.b64 %0,{%1,%2};" : "=l"(r) : "f"(lo), "f"(hi)); return r;
}
__device__ __forceinline__ void upk(ull p, float& lo, float& hi) {
    asm("mov.b64 {%0,%1},%2;" : "=f"(lo), "=f"(hi) : "l"(p));
}
__device__ __forceinline__ ull mul2(ull a, ull b) {
    ull r; asm("mul.rn.f32x2 %0,%1,%2;" : "=l"(r) : "l"(a), "l"(b)); return r;
}
__device__ __forceinline__ ull add2(ull a, ull b) {
    ull r; asm("add.rn.f32x2 %0,%1,%2;" : "=l"(r) : "l"(a), "l"(b)); return r;
}
__device__ __forceinline__ ull fma2(ull a, ull b, ull c) {
    ull r; asm("fma.rn.f32x2 %0,%1,%2,%3;" : "=l"(r) : "l"(a), "l"(b), "l"(c)); return r;
}

// Build F and zero the output (radon half-blocks combine via atomicAdd).
__global__ __launch_bounds__(256) void prep_kernel(const float* __restrict__ x,
                                                   float* __restrict__ out) {
    int i = blockIdx.x * blockDim.x + threadIdx.x;    // 65536 threads
    int y  = i >> 7;            // 0..511
    int x4 = i & 127;           // float4-group within row
    const float4* B0 = (const float4*)x;
    const float4* B1 = (const float4*)(x + NPIX);
    float4 a  = B0[y * 128 + x4];
    float4 b  = B1[y * 128 + x4];
    float4 am = B0[(511 - y) * 128 + x4];
    float4 bm = B1[(511 - y) * 128 + x4];
    float4* o = &g_xf[(y << 9) + (x4 << 2)];
    o[0] = make_float4(a.x, b.x, am.x, bm.x);
    o[1] = make_float4(a.y, b.y, am.y, bm.y);
    o[2] = make_float4(a.z, b.z, am.z, bm.z);
    o[3] = make_float4(a.w, b.w, am.w, bm.w);
    if (i < (2 * NVIEW * IMG) / 4) {                  // 184320 floats
        ((float4*)out)[i] = make_float4(0.f, 0.f, 0.f, 0.f);
    }
}

// Paired body: outputs (vA, w) and, if hasB, (vB=180-vA, 511-w) with a shared
// gather. Bitwise (given cs[vB]==(-c,s)): gx mirror-shared; gyB_raw = -gyA.
// B row usually 511-iyA (F .zw), with an exact per-lane predicated repair
// load for the rare tie cases. Invalid only if gx>1 or own gy>1 (s>=0; the
// -1 clamp maps to valid index 0); gx>1 is shared -> gx clip valid for both.
template<int LOGW>
__device__ __forceinline__ void radon_pair_body(float* __restrict__ out,
                                                int vA, int vB, bool hasB,
                                                float2 cs, int wblock,
                                                int lo, int hi_) {
    constexpr int W  = 1 << LOGW;
    constexpr int H  = 32 >> LOGW;
    constexpr int NC = 16 / W;     // w-chunks per warp
    constexpr int G  = W / 4;      // h-steps per outer iter (G*NC == 4)

    const int lane = threadIdx.x & 31;
    const int warp = threadIdx.x >> 5;
    const int wi   = lane & (W - 1);
    const int hi   = lane >> LOGW;
    const int wbase = (wblock << 6) + (warp << 4);

    const float c = cs.x, s = cs.y;
    const ull csP  = pk(s, c);          // (s, c)
    const ull sgnP = pk(-1.0f, 1.0f);   // gx = P - s*gy0 ; gy = S + c*gy0

    ull PS[NC], accA[NC], accB[NC];
    #pragma unroll
    for (int j = 0; j < NC; j++) {
        int w = wbase + j * W + wi;
        float gx0 = __fmaf_rn((float)w, 1.0f / 256.0f, -511.0f / 512.0f);  // exact
        PS[j] = pk(__fmul_rn(c, gx0), __fmul_rn(s, gx0));   // (P, S)
        accA[j] = 0ull; accB[j] = 0ull;
    }

    // gx-clip (valid for BOTH views): all lanes gx>1 while gy0 < (m1-1)/s.
    int to_s = lo, to_e = hi_;
    if (s > 1e-6f) {
        float gx0a = __fmaf_rn((float)wbase,        1.0f / 256.0f, -511.0f / 512.0f);
        float gx0b = __fmaf_rn((float)(wbase + 15), 1.0f / 256.0f, -511.0f / 512.0f);
        float m1 = fminf(c * gx0a, c * gx0b);   // min over lanes of c*gx0
        if (m1 > 1.0f) {
            float hT = (m1 - 1.0f) / s * 256.0f + 255.5f;
            int t = (int)floorf(hT * 0.125f) - 1;        // conservative margin
            if (t > to_s) to_s = t;
            if (to_e < to_s) to_e = to_s;
        }
    }

    // gy0 starts at h = hi + 8*to_s; all values and increments exact in fp32
    float gy0 = __fmaf_rn((float)(hi + 8 * to_s), 1.0f / 256.0f, -511.0f / 512.0f);
    ull gy0p = pk(gy0, gy0);
    const ull stepP = pk((float)H / 256.0f, (float)H / 256.0f);

    const float MAGIC = 12582912.0f;      // 1.5*2^23: magic round-half-even
    const float BOUND = 12583424.0f;      // MAGIC + 512
    const unsigned MAGICI = 0x4B400000u;
    const unsigned ROWSUM = 0x96800000u + 511u;   // 2*MAGICI + 511
    const unsigned OFF    = MAGICI * 513u;        // (mod 2^32)
    const ull ONE2 = pk(1.0f, 1.0f);
    const ull C256 = pk(256.0f, 256.0f);
    const ull MH2  = pk(-0.5f, -0.5f);
    const ull MAG2 = pk(MAGIC, MAGIC);

    #pragma unroll 1
    for (int to = to_s; to < to_e; to++) {
        #pragma unroll
        for (int g = 0; g < G; g++) {
            ull qp = mul2(gy0p, csP);         // (s*gy0, c*gy0), each rounded once
            gy0p = add2(gy0p, stepP);         // exact
            #pragma unroll
            for (int j = 0; j < NC; j++) {
                ull gp = fma2(qp, sgnP, PS[j]);   // (gx, gyA) = ref-exact
                float gxv, gyv; upk(gp, gxv, gyv);
                ull up = add2(gp, ONE2);          // fl(clamp(g,-1)+1)==fmax(fl(g+1),0)
                float ux, uyA; upk(up, ux, uyA);
                ux  = fmaxf(ux, 0.0f);
                uyA = fmaxf(uyA, 0.0f);
                ull rp = add2(fma2(pk(ux, uyA), C256, MH2), MAG2);
                float rx, ryA; upk(rp, rx, ryA);
                // B chain (exact, independent): gyB_raw = -gyA bitwise
                float uyB = fmaxf(__fsub_rn(1.0f, gyv), 0.0f);
                float ryB = __fadd_rn(__fmaf_rn(uyB, 256.0f, -0.5f), MAGIC);
                bool okA = fmaxf(rx, ryA) < BOUND;
                bool okB = fmaxf(rx, ryB) < BOUND;
                unsigned ra  = __float_as_uint(ryA);
                unsigned rb  = __float_as_uint(ryB);
                unsigned rxb = __float_as_uint(rx);
                unsigned rowB = okA ? ra : (ROWSUM - rb);
                unsigned idx  = rowB * 512u + rxb - OFF;
                unsigned idxS = (okA | okB) ? idx : 0u;    // safe when both invalid
                float4 val = __ldg(&g_xf[idxS]);
                if (okA) accA[j] = add2(accA[j], pk(val.x, val.y));
                bool match = (rowB + rb == ROWSUM);        // loaded row == 511-iyB
                ull bv = pk(val.z, val.w);
                if (okB && !match) {                       // rare ties: exact repair
                    float4 v2 = __ldg(&g_xf[rb * 512u + rxb - OFF]);
                    bv = pk(v2.x, v2.y);
                }
                if (okB) accB[j] = add2(accB[j], bv);
            }
        }
    }

    // reduce over the H h-lanes, then atomically accumulate (exactly 2
    // commutative adds per zeroed cell -> deterministic)
    #pragma unroll
    for (int j = 0; j < NC; j++) {
        float a0, a1; upk(accA[j], a0, a1);
        float b0, b1; upk(accB[j], b0, b1);
        #pragma unroll
        for (int off = W; off < 32; off <<= 1) {
            a0 += __shfl_xor_sync(0xffffffffu, a0, off);
            a1 += __shfl_xor_sync(0xffffffffu, a1, off);
            b0 += __shfl_xor_sync(0xffffffffu, b0, off);
            b1 += __shfl_xor_sync(0xffffffffu, b1, off);
        }
        if (hi == 0) {
            int w = wbase + j * W + wi;
            atomicAdd(&out[vA * IMG + w],               a0 * (1.0f / 512.0f));
            atomicAdd(&out[NVIEW * IMG + vA * IMG + w], a1 * (1.0f / 512.0f));
            if (hasB) {
                int wm = 511 - w;
                atomicAdd(&out[vB * IMG + wm],               b0 * (1.0f / 512.0f));
                atomicAdd(&out[NVIEW * IMG + vB * IMG + wm], b1 * (1.0f / 512.0f));
            }
        }
    }
}

// 1D cost-stratified launch: item = vA | wblock<<8 | half<<11 | hasB<<12,
// sorted by descending modeled cost. Wave-1 bid->SM placement is round-robin
// across SMs, so consecutive ranks land on distinct SMs -> each SM receives a
// stratified cost sample -> flat drain.
__global__ __launch_bounds__(128, 10) void radon_kernel(float* __restrict__ out, Params p) {
    const unsigned it = p.items[blockIdx.x];
    const int vA     = it & 255;
    const int wblock = (it >> 8) & 7;
    const int half   = (it >> 11) & 1;
    const bool hasB  = (it >> 12) & 1;
    const int vB = NVIEW - vA;
    const int lo = 32 * half, hi_ = lo + 32;
    const float2 cs = p.cs[vA];
    switch (p.lw[vA]) {
        case 2: radon_pair_body<2>(out, vA, vB, hasB, cs, wblock, lo, hi_); break;
        case 3: radon_pair_body<3>(out, vA, vB, hasB, cs, wblock, lo, hi_); break;
        default: radon_pair_body<4>(out, vA, vB, hasB, cs, wblock, lo, hi_); break;
    }
}

extern "C" void kernel_launch(void* const* d_in, const int* in_sizes, int n_in,
                              void* d_out, int out_size) {
    const float* x = (const float*)d_in[0];
    float* out = (float*)d_out;

    prep_kernel<<<256, 256>>>(x, out);

    static Params p;
    static double vcost[NVIEW];
    for (int v = 0; v < NVIEW; v++) {
        double th = (double)v * (M_PI / 180.0);
        p.cs[v] = make_float2((float)cos(th), (float)sin(th));
        double ac = fabs(cos(th)), as = fabs(sin(th));
        int best = 2; double bestcost = 1e30;
        for (int lw = 2; lw <= 4; lw++) {
            double W = (double)(1 << lw), H = 32.0 / W;
            double rows = W * as + H * ac + 1.0;
            double segB = (W * ac + H * as) * 16.0 + 16.0;   // 16B pixels
            double cc = rows * (1.0 + segB / 128.0);
            if (cc < bestcost) { bestcost = cc; best = lw; }
        }
        p.lw[v] = (unsigned char)best;
        vcost[v] = bestcost;
    }
    // Mirror-trig identity (expected to hold bitwise).
    bool paired = true;
    for (int v = 1; v <= 89; v++) {
        float2 a = p.cs[v], b = p.cs[NVIEW - v];
        if (b.x != -a.x || b.y != a.y) { paired = false; break; }
    }

    // Build work items with modeled cost (replicates the device clip window).
    static unsigned short ibuf[MAXITEMS];
    static double icost[MAXITEMS];
    static int order[MAXITEMS];
    int n = 0;
    int nv = paired ? 91 : NVIEW;
    for (int pi = 0; pi < nv; pi++) {
        int vA = pi;
        bool hasB = paired && vA >= 1 && vA <= 89;
        float c = p.cs[vA].x, s = p.cs[vA].y;
        for (int half = 0; half < 2; half++) {
            for (int wb = 0; wb < 8; wb++) {
                int lo = 32 * half, hi_ = lo + 32;
                int worst = 0;
                for (int k = 0; k < 4; k++) {
                    int wbase = wb * 64 + k * 16;
                    int to_s = lo;
                    if (s > 1e-6f) {
                        double gx0a = wbase / 256.0 - 511.0 / 512.0;
                        double gx0b = (wbase + 15) / 256.0 - 511.0 / 512.0;
                        double m1 = fmin((double)c * gx0a, (double)c * gx0b);
                        if (m1 > 1.0) {
                            double hT = (m1 - 1.0) / s * 256.0 + 255.5;
                            int t = (int)floor(hT * 0.125) - 1;
                            if (t > to_s) to_s = t;
                        }
                    }
                    int iters = hi_ - to_s; if (iters < 0) iters = 0;
                    if (iters > worst) worst = iters;
                }
                ibuf[n]  = (unsigned short)(vA | (wb << 8) | (half << 11) | ((hasB ? 1 : 0) << 12));
                icost[n] = (double)worst * vcost[vA] * (hasB ? 1.15 : 1.0);
                order[n] = n;
                n++;
            }
        }
    }
    std::sort(order, order + n, [&](int a, int b) { return icost[a] > icost[b]; });
    for (int i = 0; i < n; i++) p.items[i] = ibuf[order[i]];

    radon_kernel<<<n, 128>>>(out, p);
}